// round 10
// baseline (speedup 1.0000x reference)
#include <cuda_runtime.h>
#include <cuda_fp16.h>
#include <cstdint>

// Problem constants
#define NB   4096      // batch
#define HH   64        // hidden
#define NG   192       // 3*H gates
#define TPB  256       // 8 warps, ONE 16-row group; each warp owns 1 gate-block
#define RPG  16        // rows per CTA (m16 MMA tile)
#define NCTA (NB / RPG) // 256 CTAs -> 2 CTAs/SM -> 4 warps/SMSP

// Weight-fragment staging (init only, OVERLAID with xs+hbuf afterwards)
#define WFRAG_ENTRIES (3 * 24 * 4 * 32)   // 9216 uint2 = 73728 B
#define OVERLAY_BYTES (WFRAG_ENTRIES * 8)

// h-exchange buffers: 16 rows x 72 halves (pad kills bank conflicts)
#define HPAD 72
#define HBUF_HALVES (RPG * HPAD)          // 1152 halves = 2304 B

#define WF(m, nt, s) wfrag[((((m) * 24 + (nt)) * 4 + (s)) * 32) + lane]

__device__ __forceinline__ void mma16816(float c[4], const uint32_t a[4], const uint2 b) {
    asm volatile(
        "mma.sync.aligned.m16n8k16.row.col.f32.f16.f16.f32 "
        "{%0,%1,%2,%3}, {%4,%5,%6,%7}, {%8,%9}, {%0,%1,%2,%3};\n"
        : "+f"(c[0]), "+f"(c[1]), "+f"(c[2]), "+f"(c[3])
        : "r"(a[0]), "r"(a[1]), "r"(a[2]), "r"(a[3]), "r"(b.x), "r"(b.y));
}

// fp32 single-MUFU nonlinearities (tanh.approx.f32) — rel_err ~8e-5 proven
__device__ __forceinline__ float tanh_fast(float v) {
    float t;
    asm("tanh.approx.f32 %0, %1;" : "=f"(t) : "f"(v));
    return t;
}
__device__ __forceinline__ float sigm(float v) {
    return fmaf(0.5f, tanh_fast(0.5f * v), 0.5f);
}
__device__ __forceinline__ uint32_t packh2(float a, float b) {
    half2 h = __floats2half2_rn(a, b);   // .x = a (low)
    return *reinterpret_cast<uint32_t*>(&h);
}

__global__ void __launch_bounds__(TPB, 2)
gru_fused_kernel(const float* __restrict__ x,
                 const float* __restrict__ w_ih0, const float* __restrict__ w_hh0,
                 const float* __restrict__ b_ih0, const float* __restrict__ b_hh0,
                 const float* __restrict__ w_ih1, const float* __restrict__ w_hh1,
                 const float* __restrict__ b_ih1, const float* __restrict__ b_hh1,
                 const float* __restrict__ fc_w, const float* __restrict__ fc_b,
                 float* __restrict__ out, int T)
{
    extern __shared__ unsigned char smem[];
    // Overlay [0, OVERLAY_BYTES): wfrag staging during init; then xs + hbufs.
    uint2* wfrag = reinterpret_cast<uint2*>(smem);
    __half* xs   = reinterpret_cast<__half*>(smem);                         // [T][16] fp16 = 16384 B
    __half* hbuf = reinterpret_cast<__half*>(smem + (size_t)RPG * 512 * 2); // h1s, h2s: 2 x 2304 B
    // Persistent region:
    float* fbase  = reinterpret_cast<float*>(smem + OVERLAY_BYTES);
    float* brz0s  = fbase;             // 128: bih0+bhh0 (r,z)
    float* bihN0s = brz0s + 128;       // 64
    float* bhhN0s = bihN0s + 64;       // 64
    float* wih0s  = bhhN0s + 64;       // 192
    float* brz1s  = wih0s + NG;        // 128: bih1+bhh1 (r,z)
    float* bihN1s = brz1s + 128;       // 64
    float* bhhN1s = bihN1s + 64;       // 64
    float* fcws   = bhhN1s + 64;       // 64
    float* fcbs   = fcws + HH;         // 1
    float* fcpart = fcbs + 1;          // 128 (8 warps x 16 rows)

    const int tid  = threadIdx.x;
    const int lane = tid & 31;
    const int wg   = tid >> 5;         // warp 0..7, owns gate-block g = wg

    // ---- one-time: pack B-fragments (fp16) into overlay staging ----
    for (int i = tid; i < WFRAG_ENTRIES; i += TPB) {
        int l  = i & 31;
        int s  = (i >> 5) & 3;
        int nt = (i >> 7) % 24;
        int m  = (i >> 7) / 24;
        const float* W = (m == 0) ? w_hh0 : ((m == 1) ? w_ih1 : w_hh1);
        const float* row = W + (nt * 8 + (l >> 2)) * HH;
        int k0 = s * 16 + 2 * (l & 3);
        uint2 e;
        e.x = packh2(row[k0],     row[k0 + 1]);
        e.y = packh2(row[k0 + 8], row[k0 + 9]);
        wfrag[i] = e;
    }
    for (int i = tid; i < 128; i += TPB) {
        brz0s[i] = b_ih0[i] + b_hh0[i];
        brz1s[i] = b_ih1[i] + b_hh1[i];
    }
    if (tid < 64) {
        bihN0s[tid] = b_ih0[128 + tid];
        bhhN0s[tid] = b_hh0[128 + tid];
        bihN1s[tid] = b_ih1[128 + tid];
        bhhN1s[tid] = b_hh1[128 + tid];
        fcws[tid]   = fc_w[tid];
    }
    for (int i = tid; i < NG; i += TPB) wih0s[i] = w_ih0[i];
    if (tid == 0) fcbs[0] = fc_b[0];
    __syncthreads();

    // ---- copy this warp's B-fragments to registers (compile-time indices only) ----
    // One gate-block per warp: kind k in {r,z,n} -> n-tile 8k + wg
    uint2 wfh0[3][4], wfi1[3][4], wfh1[3][4];
    #pragma unroll
    for (int k = 0; k < 3; ++k) {
        const int nt = 8 * k + wg;
        #pragma unroll
        for (int s = 0; s < 4; ++s) {
            wfh0[k][s] = WF(0, nt, s);
            wfi1[k][s] = WF(1, nt, s);
            wfh1[k][s] = WF(2, nt, s);
        }
    }
    __syncthreads();   // staging fully consumed; overlay may be overwritten

    // ---- stage x for this CTA's 16 rows into overlay (fp16) ----
    {
        const int base = blockIdx.x * RPG;
        for (int i = tid; i < RPG * T; i += TPB) {
            int row = i / T;
            int t   = i - row * T;
            xs[t * RPG + row] = __float2half(x[(size_t)(base + row) * T + t]);
        }
    }
    __syncthreads();

    const int rowbase = blockIdx.x * RPG;
    const int q  = lane & 3;
    const int r0 = lane >> 2;

    __half* h1s = hbuf;
    __half* h2s = hbuf + HBUF_HALVES;

    float    h1c[4], h2c[4];           // fp32 carry for this warp's 8 columns
    uint32_t hA1[16], hA2[16];
    #pragma unroll
    for (int i = 0; i < 4; i++) { h1c[i] = 0.0f; h2c[i] = 0.0f; }
    #pragma unroll
    for (int i = 0; i < 16; i++) { hA1[i] = 0u; hA2[i] = 0u; }

    const float2* brz0p  = reinterpret_cast<const float2*>(brz0s);
    const float2* bihN0p = reinterpret_cast<const float2*>(bihN0s);
    const float2* bhhN0p = reinterpret_cast<const float2*>(bhhN0s);
    const float2* wih0p  = reinterpret_cast<const float2*>(wih0s);
    const float2* brz1p  = reinterpret_cast<const float2*>(brz1s);
    const float2* bihN1p = reinterpret_cast<const float2*>(bihN1s);
    const float2* bhhN1p = reinterpret_cast<const float2*>(bhhN1s);
    const float2* fcwp   = reinterpret_cast<const float2*>(fcws);

    const int j0 = 8 * wg + 2 * q;     // this warp's output column pair

    for (int t = 0; t < T; ++t) {
        float x0 = __half2float(xs[t * RPG + r0]);
        float x1 = __half2float(xs[t * RPG + r0 + 8]);

        // ================= layer 0 (this warp: 1 gate-block, 12 MMAs) =============
        {
            float2 bR = brz0p[      4 * wg + q];
            float2 bZ = brz0p[32 +  4 * wg + q];
            float2 bN = bhhN0p[4 * wg + q];
            float cr[4] = {bR.x, bR.y, bR.x, bR.y};
            float cz[4] = {bZ.x, bZ.y, bZ.x, bZ.y};
            float cn[4] = {bN.x, bN.y, bN.x, bN.y};
            #pragma unroll
            for (int s = 0; s < 4; ++s) {
                mma16816(cr, &hA1[4 * s], wfh0[0][s]);
                mma16816(cz, &hA1[4 * s], wfh0[1][s]);
                mma16816(cn, &hA1[4 * s], wfh0[2][s]);
            }
            float2 wR = wih0p[     4 * wg + q];
            float2 wZ = wih0p[32 + 4 * wg + q];
            float2 wN = wih0p[64 + 4 * wg + q];
            float2 pN = bihN0p[4 * wg + q];
            float xr[4]  = {x0, x0, x1, x1};
            float wRr[4] = {wR.x, wR.y, wR.x, wR.y};
            float wZr[4] = {wZ.x, wZ.y, wZ.x, wZ.y};
            float wNr[4] = {wN.x, wN.y, wN.x, wN.y};
            float pNr[4] = {pN.x, pN.y, pN.x, pN.y};
            float hn[4];
            #pragma unroll
            for (int i = 0; i < 4; ++i) {
                float rr = sigm(fmaf(xr[i], wRr[i], cr[i]));
                float zz = sigm(fmaf(xr[i], wZr[i], cz[i]));
                float in_ = fmaf(xr[i], wNr[i], pNr[i]);
                float nn = tanh_fast(fmaf(rr, cn[i], in_));
                float hp = h1c[i];
                float hv = fmaf(zz, hp - nn, nn);
                h1c[i] = hv;
                hn[i] = hv;
            }
            *reinterpret_cast<uint32_t*>(&h1s[r0 * HPAD + j0])       = packh2(hn[0], hn[1]);
            *reinterpret_cast<uint32_t*>(&h1s[(r0 + 8) * HPAD + j0]) = packh2(hn[2], hn[3]);
        }
        __syncthreads();
        #pragma unroll
        for (int s = 0; s < 4; ++s) {
            hA1[4 * s + 0] = *reinterpret_cast<const uint32_t*>(&h1s[r0 * HPAD + 16 * s + 2 * q]);
            hA1[4 * s + 1] = *reinterpret_cast<const uint32_t*>(&h1s[(r0 + 8) * HPAD + 16 * s + 2 * q]);
            hA1[4 * s + 2] = *reinterpret_cast<const uint32_t*>(&h1s[r0 * HPAD + 16 * s + 8 + 2 * q]);
            hA1[4 * s + 3] = *reinterpret_cast<const uint32_t*>(&h1s[(r0 + 8) * HPAD + 16 * s + 8 + 2 * q]);
        }

        // ================= layer 1 (this warp: 1 gate-block, 24 MMAs) =============
        {
            float2 bR  = brz1p[      4 * wg + q];
            float2 bZ  = brz1p[32 +  4 * wg + q];
            float2 biN = bihN1p[4 * wg + q];
            float2 bhN = bhhN1p[4 * wg + q];
            // r,z: h-part accumulates straight onto merged bias (order-of-add only)
            float air[4] = {bR.x, bR.y, bR.x, bR.y};
            float aiz[4] = {bZ.x, bZ.y, bZ.x, bZ.y};
            float ain[4] = {biN.x, biN.y, biN.x, biN.y};
            float dn[4]  = {bhN.x, bhN.y, bhN.x, bhN.y};
            #pragma unroll
            for (int s = 0; s < 4; ++s) {
                mma16816(air, &hA2[4 * s], wfh1[0][s]);
                mma16816(aiz, &hA2[4 * s], wfh1[1][s]);
                mma16816(dn,  &hA2[4 * s], wfh1[2][s]);
                mma16816(air, &hA1[4 * s], wfi1[0][s]);
                mma16816(aiz, &hA1[4 * s], wfi1[1][s]);
                mma16816(ain, &hA1[4 * s], wfi1[2][s]);
            }
            float hn[4];
            #pragma unroll
            for (int i = 0; i < 4; ++i) {
                float rr = sigm(air[i]);
                float zz = sigm(aiz[i]);
                float nn = tanh_fast(fmaf(rr, dn[i], ain[i]));
                float hp = h2c[i];
                float hv = fmaf(zz, hp - nn, nn);
                h2c[i] = hv;
                hn[i] = hv;
            }
            *reinterpret_cast<uint32_t*>(&h2s[r0 * HPAD + j0])       = packh2(hn[0], hn[1]);
            *reinterpret_cast<uint32_t*>(&h2s[(r0 + 8) * HPAD + j0]) = packh2(hn[2], hn[3]);
        }
        __syncthreads();
        #pragma unroll
        for (int s = 0; s < 4; ++s) {
            hA2[4 * s + 0] = *reinterpret_cast<const uint32_t*>(&h2s[r0 * HPAD + 16 * s + 2 * q]);
            hA2[4 * s + 1] = *reinterpret_cast<const uint32_t*>(&h2s[(r0 + 8) * HPAD + 16 * s + 2 * q]);
            hA2[4 * s + 2] = *reinterpret_cast<const uint32_t*>(&h2s[r0 * HPAD + 16 * s + 8 + 2 * q]);
            hA2[4 * s + 3] = *reinterpret_cast<const uint32_t*>(&h2s[(r0 + 8) * HPAD + 16 * s + 8 + 2 * q]);
        }
    }

    // ---- final FC: this warp's 8 columns, then cross-warp sum via SMEM ----
    float p0, p1;
    {
        float2 fw = fcwp[4 * wg + q];
        p0 = h2c[0] * fw.x + h2c[1] * fw.y;
        p1 = h2c[2] * fw.x + h2c[3] * fw.y;
    }
    p0 += __shfl_xor_sync(0xffffffffu, p0, 1);
    p0 += __shfl_xor_sync(0xffffffffu, p0, 2);
    p1 += __shfl_xor_sync(0xffffffffu, p1, 1);
    p1 += __shfl_xor_sync(0xffffffffu, p1, 2);
    if (q == 0) {
        fcpart[wg * RPG + r0]     = p0;
        fcpart[wg * RPG + r0 + 8] = p1;
    }
    __syncthreads();
    if (wg == 0 && lane < RPG) {
        float s = fcbs[0];
        #pragma unroll
        for (int w = 0; w < 8; ++w)
            s += fcpart[w * RPG + lane];
        out[rowbase + lane] = s;
    }
}

extern "C" void kernel_launch(void* const* d_in, const int* in_sizes, int n_in,
                              void* d_out, int out_size) {
    const float* x     = (const float*)d_in[0];
    const float* w_ih0 = (const float*)d_in[1];
    const float* w_hh0 = (const float*)d_in[2];
    const float* b_ih0 = (const float*)d_in[3];
    const float* b_hh0 = (const float*)d_in[4];
    const float* w_ih1 = (const float*)d_in[5];
    const float* w_hh1 = (const float*)d_in[6];
    const float* b_ih1 = (const float*)d_in[7];
    const float* b_hh1 = (const float*)d_in[8];
    const float* fc_w  = (const float*)d_in[9];
    const float* fc_b  = (const float*)d_in[10];

    int T = in_sizes[0] / NB;   // 512

    // overlay (73728: xs 16384 + 2 hbufs 4608 fit inside) + persistent floats (897)
    size_t smem = (size_t)OVERLAY_BYTES + 897 * 4;   // 77316 B -> 2 CTAs/SM
    cudaFuncSetAttribute(gru_fused_kernel,
                         cudaFuncAttributeMaxDynamicSharedMemorySize, (int)smem);

    gru_fused_kernel<<<NCTA, TPB, smem>>>(
        x, w_ih0, w_hh0, b_ih0, b_hh0,
        w_ih1, w_hh1, b_ih1, b_hh1,
        fc_w, fc_b, (float*)d_out, T);
}

// round 11
// speedup vs baseline: 1.2086x; 1.2086x over previous
#include <cuda_runtime.h>
#include <cuda_fp16.h>
#include <cstdint>

// Problem constants
#define NB   4096      // batch
#define HH   64        // hidden
#define NG   192       // 3*H gates
#define TPB  256       // 8 warps: 2 groups x 4 warps
#define RPG  16        // rows per group (m16 MMA tile)
#define RPB  32        // rows per CTA (2 groups)
#define NCTA (NB / RPB) // 128 CTAs

// Weight-fragment staging SMEM (init only)
#define WFRAG_ENTRIES (3 * 24 * 4 * 32)   // 9216 uint2 = 73728 B
#define WFRAG_BYTES   (WFRAG_ENTRIES * 8)

// h-exchange buffer: 16 rows x 72 halves (stride 144B -> conflict-free ldmatrix)
#define HPAD 72
#define HBUF_HALVES (RPG * HPAD)

#define WF(m, nt, s) wfrag[((((m) * 24 + (nt)) * 4 + (s)) * 32) + lane]

__device__ __forceinline__ void mma16816(float c[4], const uint32_t a[4], const uint2 b) {
    asm volatile(
        "mma.sync.aligned.m16n8k16.row.col.f32.f16.f16.f32 "
        "{%0,%1,%2,%3}, {%4,%5,%6,%7}, {%8,%9}, {%0,%1,%2,%3};\n"
        : "+f"(c[0]), "+f"(c[1]), "+f"(c[2]), "+f"(c[3])
        : "r"(a[0]), "r"(a[1]), "r"(a[2]), "r"(a[3]), "r"(b.x), "r"(b.y));
}

__device__ __forceinline__ void ldmatrix4(uint32_t* d, uint32_t addr) {
    asm volatile(
        "ldmatrix.sync.aligned.m8n8.x4.shared.b16 {%0,%1,%2,%3}, [%4];"
        : "=r"(d[0]), "=r"(d[1]), "=r"(d[2]), "=r"(d[3]) : "r"(addr));
}
__device__ __forceinline__ void stmatrix4(uint32_t addr, uint32_t a, uint32_t b,
                                          uint32_t c, uint32_t d) {
    asm volatile(
        "stmatrix.sync.aligned.m8n8.x4.shared.b16 [%0], {%1,%2,%3,%4};"
        :: "r"(addr), "r"(a), "r"(b), "r"(c), "r"(d) : "memory");
}

// fp32 single-MUFU nonlinearities (tanh.approx.f32) — rel_err ~8e-5 proven
__device__ __forceinline__ float tanh_fast(float v) {
    float t;
    asm("tanh.approx.f32 %0, %1;" : "=f"(t) : "f"(v));
    return t;
}
__device__ __forceinline__ float sigm(float v) {
    return fmaf(0.5f, tanh_fast(0.5f * v), 0.5f);
}
__device__ __forceinline__ uint32_t packh2(float a, float b) {
    half2 h = __floats2half2_rn(a, b);   // .x = a (low)
    return *reinterpret_cast<uint32_t*>(&h);
}

__global__ void __launch_bounds__(TPB, 1)
gru_fused_kernel(const float* __restrict__ x,
                 const float* __restrict__ w_ih0, const float* __restrict__ w_hh0,
                 const float* __restrict__ b_ih0, const float* __restrict__ b_hh0,
                 const float* __restrict__ w_ih1, const float* __restrict__ w_hh1,
                 const float* __restrict__ b_ih1, const float* __restrict__ b_hh1,
                 const float* __restrict__ fc_w, const float* __restrict__ fc_b,
                 float* __restrict__ out, int T)
{
    extern __shared__ unsigned char smem[];
    uint2* wfrag = reinterpret_cast<uint2*>(smem);
    __half* xs   = reinterpret_cast<__half*>(smem + WFRAG_BYTES);          // [T][32] fp16
    __half* hbuf = reinterpret_cast<__half*>(smem + WFRAG_BYTES + (size_t)RPB * T * 2);
    float* fbase = reinterpret_cast<float*>(reinterpret_cast<unsigned char*>(hbuf) + 4 * HBUF_HALVES * 2);
    float* brz0s  = fbase;             // 128: bih0+bhh0 (r,z)
    float* bihN0s = brz0s + 128;       // 64
    float* bhhN0s = bihN0s + 64;       // 64
    float* wih0s  = bhhN0s + 64;       // 192
    float* brz1s  = wih0s + NG;        // 128: bih1+bhh1 (r,z)
    float* bihN1s = brz1s + 128;       // 64
    float* bhhN1s = bihN1s + 64;       // 64
    float* fcws   = bhhN1s + 64;       // 64
    float* fcbs   = fcws + HH;         // 1
    float* fcpart = fcbs + 1;          // 128

    const int tid = threadIdx.x;

    // ---- one-time weight prep: pack B-fragments (fp16) into staging SMEM ----
    for (int i = tid; i < WFRAG_ENTRIES; i += TPB) {
        int lane = i & 31;
        int s    = (i >> 5) & 3;
        int nt   = (i >> 7) % 24;
        int m    = (i >> 7) / 24;
        const float* W = (m == 0) ? w_hh0 : ((m == 1) ? w_ih1 : w_hh1);
        const float* row = W + (nt * 8 + (lane >> 2)) * HH;
        int k0 = s * 16 + 2 * (lane & 3);
        uint2 e;
        e.x = packh2(row[k0],     row[k0 + 1]);
        e.y = packh2(row[k0 + 8], row[k0 + 9]);
        wfrag[i] = e;
    }
    for (int i = tid; i < 128; i += TPB) {
        brz0s[i] = b_ih0[i] + b_hh0[i];
        brz1s[i] = b_ih1[i] + b_hh1[i];
    }
    for (int i = tid; i < 64; i += TPB) {
        bihN0s[i] = b_ih0[128 + i];
        bhhN0s[i] = b_hh0[128 + i];
        bihN1s[i] = b_ih1[128 + i];
        bhhN1s[i] = b_hh1[128 + i];
        fcws[i]   = fc_w[i];
    }
    for (int i = tid; i < NG; i += TPB) wih0s[i] = w_ih0[i];
    if (tid == 0) fcbs[0] = fc_b[0];

    // ---- stage x (fp16), coalesced ----
    {
        const int base = blockIdx.x * RPB;
        for (int i = tid; i < RPB * T; i += TPB) {
            int row = i / T;
            int t   = i - row * T;
            xs[t * RPB + row] = __float2half(x[(size_t)(base + row) * T + t]);
        }
    }
    __syncthreads();

    const int lane  = tid & 31;
    const int warp  = tid >> 5;
    const int group = warp >> 2;
    const int wg    = warp & 3;        // owns gate-blocks {2wg, 2wg+1}
    const int rowbase = blockIdx.x * RPB + group * RPG;
    const int q  = lane & 3;
    const int r0 = lane >> 2;
    const int barid = group + 1;

    __half* h1sg = hbuf + group * HBUF_HALVES;
    __half* h2sg = hbuf + (2 + group) * HBUF_HALVES;
    const __half* xsg = xs + group * RPG;

    // matrix-op addresses: lane l -> row (l&15), col-half offset 8*(l>>4)
    const uint32_t h1b = (uint32_t)__cvta_generic_to_shared(h1sg);
    const uint32_t h2b = (uint32_t)__cvta_generic_to_shared(h2sg);
    const uint32_t aoff = ((uint32_t)(lane & 15) * HPAD + (uint32_t)((lane >> 4) << 3)) * 2;
    const uint32_t ld1 = h1b + aoff;               // + 32*s per k-slab
    const uint32_t ld2 = h2b + aoff;
    const uint32_t st1 = h1b + aoff + 32u * wg;    // own 16-col block at col 16*wg
    const uint32_t st2 = h2b + aoff + 32u * wg;

    // ---- hoist this warp's B-fragments into registers ----
    uint2 wfh0[2][3][4], wfi1[2][3][4], wfh1[2][3][4];
    #pragma unroll
    for (int gi = 0; gi < 2; ++gi) {
        const int g = 2 * wg + gi;
        #pragma unroll
        for (int k = 0; k < 3; ++k) {
            const int nt = 8 * k + g;
            #pragma unroll
            for (int s = 0; s < 4; ++s) {
                wfh0[gi][k][s] = WF(0, nt, s);
                wfi1[gi][k][s] = WF(1, nt, s);
                wfh1[gi][k][s] = WF(2, nt, s);
            }
        }
    }

    float    h1c[8], h2c[8];
    uint32_t hA1[16], hA2[16];
    #pragma unroll
    for (int i = 0; i < 8; i++) { h1c[i] = 0.0f; h2c[i] = 0.0f; }
    #pragma unroll
    for (int i = 0; i < 16; i++) { hA1[i] = 0u; hA2[i] = 0u; }

    const float2* brz0p  = reinterpret_cast<const float2*>(brz0s);
    const float2* bihN0p = reinterpret_cast<const float2*>(bihN0s);
    const float2* bhhN0p = reinterpret_cast<const float2*>(bhhN0s);
    const float2* wih0p  = reinterpret_cast<const float2*>(wih0s);
    const float2* brz1p  = reinterpret_cast<const float2*>(brz1s);
    const float2* bihN1p = reinterpret_cast<const float2*>(bihN1s);
    const float2* bhhN1p = reinterpret_cast<const float2*>(bhhN1s);
    const float2* fcwp   = reinterpret_cast<const float2*>(fcws);

    for (int t = 0; t < T; ++t) {
        float x0 = __half2float(xsg[t * RPB + r0]);
        float x1 = __half2float(xsg[t * RPB + r0 + 8]);

        // ================= layer 0 =================
        uint32_t s0, s1, s2, s3;   // own 16-col block fragments for stmatrix
        #pragma unroll
        for (int gi = 0; gi < 2; ++gi) {
            const int g = 2 * wg + gi;
            float2 bR = brz0p[      4 * g + q];
            float2 bZ = brz0p[32 +  4 * g + q];
            float2 bN = bhhN0p[4 * g + q];
            float cr[4] = {bR.x, bR.y, bR.x, bR.y};
            float cz[4] = {bZ.x, bZ.y, bZ.x, bZ.y};
            float cn[4] = {bN.x, bN.y, bN.x, bN.y};
            #pragma unroll
            for (int s = 0; s < 4; ++s) {
                mma16816(cr, &hA1[4 * s], wfh0[gi][0][s]);
                mma16816(cz, &hA1[4 * s], wfh0[gi][1][s]);
                mma16816(cn, &hA1[4 * s], wfh0[gi][2][s]);
            }
            float2 wR = wih0p[     4 * g + q];
            float2 wZ = wih0p[32 + 4 * g + q];
            float2 wN = wih0p[64 + 4 * g + q];
            float2 pN = bihN0p[4 * g + q];
            float xr[4]  = {x0, x0, x1, x1};
            float wRr[4] = {wR.x, wR.y, wR.x, wR.y};
            float wZr[4] = {wZ.x, wZ.y, wZ.x, wZ.y};
            float wNr[4] = {wN.x, wN.y, wN.x, wN.y};
            float pNr[4] = {pN.x, pN.y, pN.x, pN.y};
            float hn[4];
            #pragma unroll
            for (int i = 0; i < 4; ++i) {
                float rr = sigm(fmaf(xr[i], wRr[i], cr[i]));
                float zz = sigm(fmaf(xr[i], wZr[i], cz[i]));
                float in_ = fmaf(xr[i], wNr[i], pNr[i]);
                float nn = tanh_fast(fmaf(rr, cn[i], in_));
                float hp = h1c[4 * gi + i];
                float hv = fmaf(zz, hp - nn, nn);
                h1c[4 * gi + i] = hv;
                hn[i] = hv;
            }
            if (gi == 0) { s0 = packh2(hn[0], hn[1]); s1 = packh2(hn[2], hn[3]); }
            else         { s2 = packh2(hn[0], hn[1]); s3 = packh2(hn[2], hn[3]); }
        }
        stmatrix4(st1, s0, s1, s2, s3);
        asm volatile("bar.sync %0, %1;" :: "r"(barid), "n"(128) : "memory");
        #pragma unroll
        for (int s = 0; s < 4; ++s) ldmatrix4(&hA1[4 * s], ld1 + 32u * s);

        // ================= layer 1 =================
        #pragma unroll
        for (int gi = 0; gi < 2; ++gi) {
            const int g = 2 * wg + gi;
            float2 bR  = brz1p[      4 * g + q];
            float2 bZ  = brz1p[32 +  4 * g + q];
            float2 biN = bihN1p[4 * g + q];
            float2 bhN = bhhN1p[4 * g + q];
            float air[4] = {bR.x, bR.y, bR.x, bR.y};
            float aiz[4] = {bZ.x, bZ.y, bZ.x, bZ.y};
            float ain[4] = {biN.x, biN.y, biN.x, biN.y};
            float dr[4]  = {0.f, 0.f, 0.f, 0.f};
            float dz[4]  = {0.f, 0.f, 0.f, 0.f};
            float dn[4]  = {bhN.x, bhN.y, bhN.x, bhN.y};
            #pragma unroll
            for (int s = 0; s < 4; ++s) {
                mma16816(air, &hA1[4 * s], wfi1[gi][0][s]);
                mma16816(aiz, &hA1[4 * s], wfi1[gi][1][s]);
                mma16816(ain, &hA1[4 * s], wfi1[gi][2][s]);
                mma16816(dr,  &hA2[4 * s], wfh1[gi][0][s]);
                mma16816(dz,  &hA2[4 * s], wfh1[gi][1][s]);
                mma16816(dn,  &hA2[4 * s], wfh1[gi][2][s]);
            }
            float hn[4];
            #pragma unroll
            for (int i = 0; i < 4; ++i) {
                float rr = sigm(air[i] + dr[i]);
                float zz = sigm(aiz[i] + dz[i]);
                float nn = tanh_fast(fmaf(rr, dn[i], ain[i]));
                float hp = h2c[4 * gi + i];
                float hv = fmaf(zz, hp - nn, nn);
                h2c[4 * gi + i] = hv;
                hn[i] = hv;
            }
            if (gi == 0) { s0 = packh2(hn[0], hn[1]); s1 = packh2(hn[2], hn[3]); }
            else         { s2 = packh2(hn[0], hn[1]); s3 = packh2(hn[2], hn[3]); }
        }
        stmatrix4(st2, s0, s1, s2, s3);
        asm volatile("bar.sync %0, %1;" :: "r"(barid), "n"(128) : "memory");
        #pragma unroll
        for (int s = 0; s < 4; ++s) ldmatrix4(&hA2[4 * s], ld2 + 32u * s);
    }

    // ---- final FC ----
    float p0 = 0.0f, p1 = 0.0f;
    #pragma unroll
    for (int gi = 0; gi < 2; ++gi) {
        const int g = 2 * wg + gi;
        float2 fw = fcwp[4 * g + q];
        p0 += h2c[4 * gi + 0] * fw.x + h2c[4 * gi + 1] * fw.y;
        p1 += h2c[4 * gi + 2] * fw.x + h2c[4 * gi + 3] * fw.y;
    }
    p0 += __shfl_xor_sync(0xffffffffu, p0, 1);
    p0 += __shfl_xor_sync(0xffffffffu, p0, 2);
    p1 += __shfl_xor_sync(0xffffffffu, p1, 1);
    p1 += __shfl_xor_sync(0xffffffffu, p1, 2);
    if (q == 0) {
        fcpart[(group * 4 + wg) * RPG + r0]     = p0;
        fcpart[(group * 4 + wg) * RPG + r0 + 8] = p1;
    }
    asm volatile("bar.sync %0, %1;" :: "r"(barid), "n"(128) : "memory");
    if (wg == 0 && lane < RPG) {
        float s = fcbs[0];
        #pragma unroll
        for (int w = 0; w < 4; ++w)
            s += fcpart[(group * 4 + w) * RPG + lane];
        out[rowbase + lane] = s;
    }
}

extern "C" void kernel_launch(void* const* d_in, const int* in_sizes, int n_in,
                              void* d_out, int out_size) {
    const float* x     = (const float*)d_in[0];
    const float* w_ih0 = (const float*)d_in[1];
    const float* w_hh0 = (const float*)d_in[2];
    const float* b_ih0 = (const float*)d_in[3];
    const float* b_hh0 = (const float*)d_in[4];
    const float* w_ih1 = (const float*)d_in[5];
    const float* w_hh1 = (const float*)d_in[6];
    const float* b_ih1 = (const float*)d_in[7];
    const float* b_hh1 = (const float*)d_in[8];
    const float* fc_w  = (const float*)d_in[9];
    const float* fc_b  = (const float*)d_in[10];

    int T = in_sizes[0] / NB;   // 512

    size_t smem = (size_t)WFRAG_BYTES
                + (size_t)RPB * T * 2
                + 4 * HBUF_HALVES * 2
                + (128 + 64 + 64 + NG + 128 + 64 + 64 + 64 + 1 + 128) * 4;
    cudaFuncSetAttribute(gru_fused_kernel,
                         cudaFuncAttributeMaxDynamicSharedMemorySize, (int)smem);

    gru_fused_kernel<<<NCTA, TPB, smem>>>(
        x, w_ih0, w_hh0, b_ih0, b_hh0,
        w_ih1, w_hh1, b_ih1, b_hh1,
        fc_w, fc_b, (float*)d_out, T);
}